// round 6
// baseline (speedup 1.0000x reference)
#include <cuda_runtime.h>
#include <cuda_fp16.h>
#include <cstdint>

// Problem constants
constexpr int CB  = 4;
constexpr int CLQ = 4096;
constexpr int CLK = 4096;
constexpr int CD  = 256;

constexpr int KT = 64;         // kv rows per tile
constexpr int NT = CLK / KT;   // 64 tiles
constexpr int STRIDE = 264;    // smem row stride (halfs) for 256-wide fp16 tiles
constexpr int SSTRIDE = 72;    // smem row stride (floats) for 64-wide fp32 S tiles
constexpr int NTHREADS = 256;

constexpr float SCALE   = 0.0625f;
constexpr float NEG_BIG = -1000000000.0f;
constexpr float LOG2E   = 1.4426950408889634f;
constexpr float MINIT   = -3.0e38f;

// static device scratch (~25.3 MB total)
__device__ __half g_kh[(size_t)CB * CLK * CD];
__device__ __half g_vh[(size_t)CB * CLK * CD];
__device__ __half g_qwh[(size_t)CB * CLQ * CD];   // qw * SCALE, fp16
__device__ float  g_m[(size_t)CB * CLQ];
__device__ float  g_l[(size_t)CB * CLQ];

// ---------------------------------------------------------------------------
// helpers
// ---------------------------------------------------------------------------
__device__ __forceinline__ float fast_ex2(float x) {
    float r; asm("ex2.approx.ftz.f32 %0, %1;" : "=f"(r) : "f"(x)); return r;
}
__device__ __forceinline__ void ldm4(uint32_t& r0, uint32_t& r1, uint32_t& r2, uint32_t& r3, uint32_t a) {
    asm volatile("ldmatrix.sync.aligned.m8n8.x4.shared.b16 {%0,%1,%2,%3}, [%4];"
                 : "=r"(r0), "=r"(r1), "=r"(r2), "=r"(r3) : "r"(a));
}
__device__ __forceinline__ void ldm4t(uint32_t& r0, uint32_t& r1, uint32_t& r2, uint32_t& r3, uint32_t a) {
    asm volatile("ldmatrix.sync.aligned.m8n8.x4.trans.shared.b16 {%0,%1,%2,%3}, [%4];"
                 : "=r"(r0), "=r"(r1), "=r"(r2), "=r"(r3) : "r"(a));
}
__device__ __forceinline__ void mma16816(float* c, uint32_t a0, uint32_t a1, uint32_t a2, uint32_t a3,
                                         uint32_t b0, uint32_t b1) {
    asm volatile("mma.sync.aligned.m16n8k16.row.col.f32.f16.f16.f32 "
                 "{%0,%1,%2,%3}, {%4,%5,%6,%7}, {%8,%9}, {%0,%1,%2,%3};"
                 : "+f"(c[0]), "+f"(c[1]), "+f"(c[2]), "+f"(c[3])
                 : "r"(a0), "r"(a1), "r"(a2), "r"(a3), "r"(b0), "r"(b1));
}
__device__ __forceinline__ uint32_t h2u(__half2 h) { return *reinterpret_cast<uint32_t*>(&h); }

__device__ __forceinline__ void cp16(uint32_t dst, const void* src) {
    asm volatile("cp.async.cg.shared.global [%0], [%1], 16;" :: "r"(dst), "l"(src));
}
__device__ __forceinline__ void cp_commit() { asm volatile("cp.async.commit_group;"); }
template <int N>
__device__ __forceinline__ void cp_wait() { asm volatile("cp.async.wait_group %0;" :: "n"(N)); }

// ---------------------------------------------------------------------------
// k/v fp32 -> fp16
// ---------------------------------------------------------------------------
__global__ void convert_kv_kernel(const float* __restrict__ k, const float* __restrict__ v) {
    size_t i = (size_t)blockIdx.x * blockDim.x + threadIdx.x;
    size_t n4 = (size_t)CB * CLK * CD / 4;
    if (i >= n4) return;
    float4 a = reinterpret_cast<const float4*>(k)[i];
    float4 b = reinterpret_cast<const float4*>(v)[i];
    __half2* kh2 = reinterpret_cast<__half2*>(g_kh);
    __half2* vh2 = reinterpret_cast<__half2*>(g_vh);
    kh2[2 * i]     = __floats2half2_rn(a.x, a.y);
    kh2[2 * i + 1] = __floats2half2_rn(a.z, a.w);
    vh2[2 * i]     = __floats2half2_rn(b.x, b.y);
    vh2[2 * i + 1] = __floats2half2_rn(b.z, b.w);
}

// ---------------------------------------------------------------------------
// qw kernel: qw = (q @ w) * SCALE -> g_qwh fp16.  grid (CLQ/128, CB), 256 thr
// ---------------------------------------------------------------------------
extern __shared__ char smem_raw[];

__global__ void __launch_bounds__(NTHREADS, 1)
qw_kernel(const float* __restrict__ q, const float* __restrict__ w) {
    __half* sQ = reinterpret_cast<__half*>(smem_raw);           // 128 x STRIDE
    __half* sW = sQ + 128 * STRIDE;                             // 64 x STRIDE

    const int tid  = threadIdx.x;
    const int lane = tid & 31;
    const int wid  = tid >> 5;
    const int b     = blockIdx.y;
    const int qbase = blockIdx.x * 128;
    const int wrow  = wid * 16;
    const int quad  = lane >> 2;
    const int qc    = lane & 3;

    const uint32_t smemB = (uint32_t)__cvta_generic_to_shared(smem_raw);
    const uint32_t aPat = (uint32_t)(((wrow + (lane & 15)) * STRIDE + ((lane >> 4) << 3)) * 2);
    const uint32_t bPatT = (uint32_t)(((((lane & 7) + (((lane >> 3) & 1) << 3)) * STRIDE) +
                                      ((lane >> 4) << 3)) * 2);

    {
        const float4* qg = reinterpret_cast<const float4*>(q + ((size_t)b * CLQ + qbase) * CD);
#pragma unroll
        for (int i = 0; i < 32; i++) {
            int e = tid + i * NTHREADS;
            int row = e >> 6, c4 = e & 63;
            float4 f = qg[row * 64 + c4];
            __half2* d = reinterpret_cast<__half2*>(sQ + row * STRIDE + c4 * 4);
            d[0] = __floats2half2_rn(f.x, f.y);
            d[1] = __floats2half2_rn(f.z, f.w);
        }
    }

    float oacc[32][4];
#pragma unroll
    for (int i = 0; i < 32; i++)
#pragma unroll
        for (int j = 0; j < 4; j++) oacc[i][j] = 0.f;

    const uint32_t bBaseW = smemB + (uint32_t)(128 * STRIDE * 2) + bPatT;
    for (int wb = 0; wb < 4; wb++) {
        __syncthreads();
        const float4* wg = reinterpret_cast<const float4*>(w + (size_t)wb * 64 * CD);
#pragma unroll
        for (int i = 0; i < 16; i++) {
            int e = tid + i * NTHREADS;
            int row = e >> 6, c4 = e & 63;
            float4 f = wg[row * 64 + c4];
            __half2* d = reinterpret_cast<__half2*>(sW + row * STRIDE + c4 * 4);
            d[0] = __floats2half2_rn(f.x, f.y);
            d[1] = __floats2half2_rn(f.z, f.w);
        }
        __syncthreads();
#pragma unroll
        for (int kk = 0; kk < 4; kk++) {
            uint32_t a0, a1, a2, a3;
            ldm4(a0, a1, a2, a3, smemB + aPat + (uint32_t)((wb * 64 + kk * 16) * 2));
#pragma unroll
            for (int nt2 = 0; nt2 < 16; nt2++) {
                uint32_t b0, b1, b2, b3;
                ldm4t(b0, b1, b2, b3, bBaseW + (uint32_t)((kk * 16 * STRIDE + nt2 * 16) * 2));
                mma16816(oacc[nt2 * 2],     a0, a1, a2, a3, b0, b1);
                mma16816(oacc[nt2 * 2 + 1], a0, a1, a2, a3, b2, b3);
            }
        }
    }

    __half2* qwRow0 = reinterpret_cast<__half2*>(g_qwh + ((size_t)b * CLQ + qbase + wrow + quad) * CD);
    __half2* qwRow1 = qwRow0 + 4 * CD;   // +8 rows (half2 units)
#pragma unroll
    for (int nt = 0; nt < 32; nt++) {
        int c2 = (nt * 8 + qc * 2) >> 1;
        qwRow0[c2] = __floats2half2_rn(oacc[nt][0] * SCALE, oacc[nt][1] * SCALE);
        qwRow1[c2] = __floats2half2_rn(oacc[nt][2] * SCALE, oacc[nt][3] * SCALE);
    }
}

// ---------------------------------------------------------------------------
// K_S: S = qw @ k^T (pre-scaled), masked -> att; per-row (m,l) -> g_m/g_l
// grid (CLQ/64, CB), 256 thr, 2 CTAs/SM
// smem: buf0 [0,33792) buf1 [33792,67584) mask/red [67584,83968)
// ---------------------------------------------------------------------------
__global__ void __launch_bounds__(NTHREADS, 2)
ks_kernel(const int* __restrict__ kidx, float* __restrict__ att) {
    const int tid  = threadIdx.x;
    const int lane = tid & 31;
    const int wid  = tid >> 5;
    const int rg   = wid & 3;     // row group (16 rows)
    const int ch   = wid >> 2;    // col half (32 of 64 tile cols)
    const int b     = blockIdx.y;
    const int qbase = blockIdx.x * 64;
    const int quad  = lane >> 2;
    const int qc    = lane & 3;

    const uint32_t smemB = (uint32_t)__cvta_generic_to_shared(smem_raw);
    int* maskS = reinterpret_cast<int*>(smem_raw + 67584);

    const uint32_t aPat = (uint32_t)(((rg * 16 + (lane & 15)) * STRIDE + ((lane >> 4) << 3)) * 2);
    const uint32_t bPatK = (uint32_t)(((((lane & 7) + ((lane >> 4) << 3)) * STRIDE) +
                                      (((lane >> 3) & 1) << 3)) * 2);
    const uint32_t bufB[2] = { smemB, smemB + 33792u };

    // ---- stage qw tile (64 x 256 fp16) into buf0, extract A fragments ----
    {
        const char* src = reinterpret_cast<const char*>(g_qwh + ((size_t)b * CLQ + qbase) * CD);
#pragma unroll
        for (int i = 0; i < 8; i++) {
            int e = tid + i * NTHREADS;         // 2048 chunks of 16B
            int row = e >> 5, c = e & 31;
            cp16(bufB[0] + (uint32_t)(row * 528 + c * 16), src + row * 512 + c * 16);
        }
    }
    // mask
#pragma unroll
    for (int i = 0; i < 4; i++) {
        int e = tid + i * NTHREADS;
        reinterpret_cast<int4*>(maskS)[e] =
            reinterpret_cast<const int4*>(kidx + (size_t)b * CLK)[e];
    }
    cp_commit(); cp_wait<0>();
    __syncthreads();

    uint32_t aQ[16][4];
#pragma unroll
    for (int kc = 0; kc < 16; kc++)
        ldm4(aQ[kc][0], aQ[kc][1], aQ[kc][2], aQ[kc][3], bufB[0] + aPat + (uint32_t)(kc * 32));
    __syncthreads();   // buf0 free

    const __half* khg = g_kh + (size_t)b * CLK * CD;
    auto load_k = [&](int kt, int buf) {
        const char* src = reinterpret_cast<const char*>(khg + (size_t)kt * KT * CD);
        uint32_t dstB = bufB[buf];
#pragma unroll
        for (int i = 0; i < 8; i++) {
            int e = tid + i * NTHREADS;
            int row = e >> 5, c = e & 31;
            cp16(dstB + (uint32_t)(row * 528 + c * 16), src + row * 512 + c * 16);
        }
    };

    float m0 = MINIT, m1 = MINIT, l0 = 0.f, l1 = 0.f;
    float* attRow0 = att + ((size_t)b * CLQ + qbase + rg * 16 + quad) * CLK;
    float* attRow1 = attRow0 + (size_t)8 * CLK;

    load_k(0, 0); cp_commit();

#pragma unroll 1
    for (int kt = 0; kt < NT; kt++) {
        if (kt + 1 < NT) {
            load_k(kt + 1, (kt + 1) & 1);
            cp_commit();
            cp_wait<1>();
        } else {
            cp_wait<0>();
        }
        __syncthreads();

        float sacc[4][4];
#pragma unroll
        for (int i = 0; i < 4; i++)
#pragma unroll
            for (int j = 0; j < 4; j++) sacc[i][j] = 0.f;

        const uint32_t bBase = bufB[kt & 1] + bPatK + (uint32_t)(ch * 32 * STRIDE * 2);
#pragma unroll
        for (int kc = 0; kc < 16; kc++) {
#pragma unroll
            for (int nt2 = 0; nt2 < 2; nt2++) {
                uint32_t b0, b1, b2, b3;
                ldm4(b0, b1, b2, b3, bBase + (uint32_t)((nt2 * 16 * STRIDE + kc * 16) * 2));
                mma16816(sacc[nt2 * 2],     aQ[kc][0], aQ[kc][1], aQ[kc][2], aQ[kc][3], b0, b1);
                mma16816(sacc[nt2 * 2 + 1], aQ[kc][0], aQ[kc][1], aQ[kc][2], aQ[kc][3], b2, b3);
            }
        }

        float rmax0 = NEG_BIG, rmax1 = NEG_BIG, s0 = 0.f, s1 = 0.f;
#pragma unroll
        for (int nt = 0; nt < 4; nt++) {
            int c0 = kt * KT + ch * 32 + nt * 8 + qc * 2;
            float f0 = maskS[c0]     ? sacc[nt][0] : NEG_BIG;
            float f1 = maskS[c0 + 1] ? sacc[nt][1] : NEG_BIG;
            float f2 = maskS[c0]     ? sacc[nt][2] : NEG_BIG;
            float f3 = maskS[c0 + 1] ? sacc[nt][3] : NEG_BIG;
            sacc[nt][0] = f0; sacc[nt][1] = f1; sacc[nt][2] = f2; sacc[nt][3] = f3;
            rmax0 = fmaxf(rmax0, fmaxf(f0, f1));
            rmax1 = fmaxf(rmax1, fmaxf(f2, f3));
            *reinterpret_cast<float2*>(attRow0 + c0) = make_float2(f0, f1);
            *reinterpret_cast<float2*>(attRow1 + c0) = make_float2(f2, f3);
        }
        rmax0 = fmaxf(rmax0, __shfl_xor_sync(0xffffffffu, rmax0, 1));
        rmax0 = fmaxf(rmax0, __shfl_xor_sync(0xffffffffu, rmax0, 2));
        rmax1 = fmaxf(rmax1, __shfl_xor_sync(0xffffffffu, rmax1, 1));
        rmax1 = fmaxf(rmax1, __shfl_xor_sync(0xffffffffu, rmax1, 2));

        float m0n = fmaxf(m0, rmax0), m1n = fmaxf(m1, rmax1);
#pragma unroll
        for (int nt = 0; nt < 4; nt++) {
            s0 += fast_ex2((sacc[nt][0] - m0n) * LOG2E) + fast_ex2((sacc[nt][1] - m0n) * LOG2E);
            s1 += fast_ex2((sacc[nt][2] - m1n) * LOG2E) + fast_ex2((sacc[nt][3] - m1n) * LOG2E);
        }
        s0 += __shfl_xor_sync(0xffffffffu, s0, 1);
        s0 += __shfl_xor_sync(0xffffffffu, s0, 2);
        s1 += __shfl_xor_sync(0xffffffffu, s1, 1);
        s1 += __shfl_xor_sync(0xffffffffu, s1, 2);

        l0 = l0 * fast_ex2((m0 - m0n) * LOG2E) + s0;
        l1 = l1 * fast_ex2((m1 - m1n) * LOG2E) + s1;
        m0 = m0n; m1 = m1n;
        __syncthreads();
    }

    // ---- combine col-halves, store stats ----
    float* redm = reinterpret_cast<float*>(smem_raw + 67584);          // [2][64]
    float* redl = reinterpret_cast<float*>(smem_raw + 67584 + 512);    // [2][64]
    __syncthreads();
    if (qc == 0) {
        redm[ch * 64 + rg * 16 + quad]     = m0;
        redm[ch * 64 + rg * 16 + quad + 8] = m1;
        redl[ch * 64 + rg * 16 + quad]     = l0;
        redl[ch * 64 + rg * 16 + quad + 8] = l1;
    }
    __syncthreads();
    if (tid < 64) {
        float ma = redm[tid], mb = redm[64 + tid];
        float m = fmaxf(ma, mb);
        float l = redl[tid] * fast_ex2((ma - m) * LOG2E) +
                  redl[64 + tid] * fast_ex2((mb - m) * LOG2E);
        g_m[(size_t)b * CLQ + qbase + tid] = m;
        g_l[(size_t)b * CLQ + qbase + tid] = l;
    }
}

// ---------------------------------------------------------------------------
// K_P: p = exp(s - m)/l -> att; O = p @ v -> out
// grid (CLQ/64, CB), 256 thr, 2 CTAs/SM
// smem: vbuf0 [0,33792) vbuf1 [33792,67584) sbuf0 [67584,86016) sbuf1 [86016,104448)
// ---------------------------------------------------------------------------
__global__ void __launch_bounds__(NTHREADS, 2)
kp_kernel(float* __restrict__ out, float* __restrict__ att) {
    const int tid  = threadIdx.x;
    const int lane = tid & 31;
    const int wid  = tid >> 5;
    const int rg   = wid & 3;     // row group (16 rows)
    const int dh   = wid >> 2;    // d half (128 cols)
    const int b     = blockIdx.y;
    const int qbase = blockIdx.x * 64;
    const int quad  = lane >> 2;
    const int qc    = lane & 3;

    const uint32_t smemB = (uint32_t)__cvta_generic_to_shared(smem_raw);
    float* sb[2] = { reinterpret_cast<float*>(smem_raw + 67584),
                     reinterpret_cast<float*>(smem_raw + 86016) };

    const uint32_t bPatT = (uint32_t)(((((lane & 7) + (((lane >> 3) & 1) << 3)) * STRIDE) +
                                      ((lane >> 4) << 3)) * 2);
    const uint32_t vBufB[2] = { smemB, smemB + 33792u };
    const uint32_t sBufB[2] = { smemB + 67584u, smemB + 86016u };

    const int r0 = rg * 16 + quad;
    const float m0   = g_m[(size_t)b * CLQ + qbase + r0];
    const float m1   = g_m[(size_t)b * CLQ + qbase + r0 + 8];
    const float invl0 = 1.0f / g_l[(size_t)b * CLQ + qbase + r0];
    const float invl1 = 1.0f / g_l[(size_t)b * CLQ + qbase + r0 + 8];

    const __half* vhg = g_vh + (size_t)b * CLK * CD;
    float* attT = att + ((size_t)b * CLQ + qbase) * CLK;
    float* attRow0 = attT + (size_t)r0 * CLK;
    float* attRow1 = attRow0 + (size_t)8 * CLK;

    auto load_vs = [&](int kt, int buf) {
        const char* vsrc = reinterpret_cast<const char*>(vhg + (size_t)kt * KT * CD);
        const char* ssrc = reinterpret_cast<const char*>(attT + (size_t)kt * KT);
#pragma unroll
        for (int i = 0; i < 8; i++) {
            int e = tid + i * NTHREADS;
            int row = e >> 5, c = e & 31;
            cp16(vBufB[buf] + (uint32_t)(row * 528 + c * 16), vsrc + row * 512 + c * 16);
        }
#pragma unroll
        for (int i = 0; i < 4; i++) {
            int e = tid + i * NTHREADS;          // 1024 chunks: 64 rows x 16
            int row = e >> 4, c = e & 15;
            cp16(sBufB[buf] + (uint32_t)(row * (SSTRIDE * 4) + c * 16),
                 ssrc + (size_t)row * CLK * 4 + c * 16);
        }
    };

    float oacc[16][4];
#pragma unroll
    for (int i = 0; i < 16; i++)
#pragma unroll
        for (int j = 0; j < 4; j++) oacc[i][j] = 0.f;

    load_vs(0, 0); cp_commit();

#pragma unroll 1
    for (int kt = 0; kt < NT; kt++) {
        if (kt + 1 < NT) {
            load_vs(kt + 1, (kt + 1) & 1);
            cp_commit();
            cp_wait<1>();
        } else {
            cp_wait<0>();
        }
        __syncthreads();

        const float* sbuf = sb[kt & 1];
        const uint32_t vBase = vBufB[kt & 1] + bPatT + (uint32_t)(dh * 128 * 2);

#pragma unroll
        for (int kc = 0; kc < 4; kc++) {
            int c = kc * 16 + qc * 2;
            float2 v00 = *reinterpret_cast<const float2*>(sbuf + r0 * SSTRIDE + c);
            float2 v10 = *reinterpret_cast<const float2*>(sbuf + (r0 + 8) * SSTRIDE + c);
            float2 v01 = *reinterpret_cast<const float2*>(sbuf + r0 * SSTRIDE + c + 8);
            float2 v11 = *reinterpret_cast<const float2*>(sbuf + (r0 + 8) * SSTRIDE + c + 8);

            float p00x = fast_ex2((v00.x - m0) * LOG2E) * invl0;
            float p00y = fast_ex2((v00.y - m0) * LOG2E) * invl0;
            float p10x = fast_ex2((v10.x - m1) * LOG2E) * invl1;
            float p10y = fast_ex2((v10.y - m1) * LOG2E) * invl1;
            float p01x = fast_ex2((v01.x - m0) * LOG2E) * invl0;
            float p01y = fast_ex2((v01.y - m0) * LOG2E) * invl0;
            float p11x = fast_ex2((v11.x - m1) * LOG2E) * invl1;
            float p11y = fast_ex2((v11.y - m1) * LOG2E) * invl1;

            if (dh == 0) {
                int col = kt * KT + c;
                *reinterpret_cast<float2*>(attRow0 + col)     = make_float2(p00x, p00y);
                *reinterpret_cast<float2*>(attRow0 + col + 8) = make_float2(p01x, p01y);
                *reinterpret_cast<float2*>(attRow1 + col)     = make_float2(p10x, p10y);
                *reinterpret_cast<float2*>(attRow1 + col + 8) = make_float2(p11x, p11y);
            }

            uint32_t a0 = h2u(__floats2half2_rn(p00x, p00y));
            uint32_t a1 = h2u(__floats2half2_rn(p10x, p10y));
            uint32_t a2 = h2u(__floats2half2_rn(p01x, p01y));
            uint32_t a3 = h2u(__floats2half2_rn(p11x, p11y));
#pragma unroll
            for (int nt2 = 0; nt2 < 8; nt2++) {
                uint32_t b0, b1, b2, b3;
                ldm4t(b0, b1, b2, b3, vBase + (uint32_t)((kc * 16 * STRIDE + nt2 * 16) * 2));
                mma16816(oacc[nt2 * 2],     a0, a1, a2, a3, b0, b1);
                mma16816(oacc[nt2 * 2 + 1], a0, a1, a2, a3, b2, b3);
            }
        }
        __syncthreads();
    }

    float* outRow0 = out + ((size_t)b * CLQ + qbase + r0) * CD + dh * 128;
    float* outRow1 = outRow0 + 8 * CD;
#pragma unroll
    for (int nt = 0; nt < 16; nt++) {
        int col = nt * 8 + qc * 2;
        *reinterpret_cast<float2*>(outRow0 + col) = make_float2(oacc[nt][0], oacc[nt][1]);
        *reinterpret_cast<float2*>(outRow1 + col) = make_float2(oacc[nt][2], oacc[nt][3]);
    }
}

// ---------------------------------------------------------------------------
// launch
// ---------------------------------------------------------------------------
extern "C" void kernel_launch(void* const* d_in, const int* in_sizes, int n_in,
                              void* d_out, int out_size) {
    const float* q    = (const float*)d_in[0];
    const float* k    = (const float*)d_in[1];
    const float* v    = (const float*)d_in[2];
    const int*   kidx = (const int*)d_in[3];
    const float* w    = (const float*)d_in[4];

    float* out = (float*)d_out;
    float* att = out + (size_t)CB * CLQ * CD;

    size_t n4 = (size_t)CB * CLK * CD / 4;
    convert_kv_kernel<<<(unsigned)((n4 + 255) / 256), 256>>>(k, v);

    cudaFuncSetAttribute(qw_kernel, cudaFuncAttributeMaxDynamicSharedMemorySize, 101376);
    qw_kernel<<<dim3(CLQ / 128, CB), NTHREADS, 101376>>>(q, w);

    cudaFuncSetAttribute(ks_kernel, cudaFuncAttributeMaxDynamicSharedMemorySize, 83968);
    ks_kernel<<<dim3(CLQ / 64, CB), NTHREADS, 83968>>>(kidx, att);

    cudaFuncSetAttribute(kp_kernel, cudaFuncAttributeMaxDynamicSharedMemorySize, 104448);
    kp_kernel<<<dim3(CLQ / 64, CB), NTHREADS, 104448>>>(out, att);
}

// round 7
// speedup vs baseline: 1.0085x; 1.0085x over previous
#include <cuda_runtime.h>
#include <cuda_fp16.h>
#include <cstdint>

// Problem constants
constexpr int CB  = 4;
constexpr int CLQ = 4096;
constexpr int CLK = 4096;
constexpr int CD  = 256;

constexpr int QT = 64;         // q rows per CTA (fused kernel)
constexpr int KT = 64;         // kv rows per tile
constexpr int NT = CLK / KT;   // 64 tiles
constexpr int STRIDE = 264;    // smem row stride (halfs) for 256-wide fp16 tiles
constexpr int USTRIDE = 72;    // smem row stride (halfs) for 64-wide u tiles
constexpr int NTHREADS = 256;

constexpr float SCALE = 0.0625f;
constexpr float LOG2E = 1.4426950408889634f;

// static device scratch (~25.3 MB)
__device__ __half g_kh[(size_t)CB * CLK * CD];
__device__ __half g_vh[(size_t)CB * CLK * CD];
__device__ __half g_qwh[(size_t)CB * CLQ * CD];   // qw * SCALE, fp16
__device__ float  g_il[(size_t)CB * CLQ];         // 1 / rowsum

// ---- fused-kernel smem layout (bytes); total 111360, 2 CTAs/SM ----
constexpr int SM_QW  = 0;        // 64 x 528  = 33792  (qw tile, resident)
constexpr int SM_B0  = 33792;    // 64 x 528  = 33792  (K even / V even)
constexpr int SM_B1  = 67584;    // 64 x 528  = 33792  (K odd  / V odd)
constexpr int SM_UH  = 101376;   // 64 x 144  = 9216   (u fp16 tile)
constexpr int SM_RED = 110592;   // 2 x 64 x 4 = 512   (l partials)
constexpr int SM_INV = 111104;   // 64 x 4    = 256    (invl)
constexpr int SM_FUSED_TOTAL = 111360;

// ---------------------------------------------------------------------------
// helpers
// ---------------------------------------------------------------------------
__device__ __forceinline__ float fast_ex2(float x) {
    float r; asm("ex2.approx.ftz.f32 %0, %1;" : "=f"(r) : "f"(x)); return r;
}
__device__ __forceinline__ void ldm4(uint32_t& r0, uint32_t& r1, uint32_t& r2, uint32_t& r3, uint32_t a) {
    asm volatile("ldmatrix.sync.aligned.m8n8.x4.shared.b16 {%0,%1,%2,%3}, [%4];"
                 : "=r"(r0), "=r"(r1), "=r"(r2), "=r"(r3) : "r"(a));
}
__device__ __forceinline__ void ldm4t(uint32_t& r0, uint32_t& r1, uint32_t& r2, uint32_t& r3, uint32_t a) {
    asm volatile("ldmatrix.sync.aligned.m8n8.x4.trans.shared.b16 {%0,%1,%2,%3}, [%4];"
                 : "=r"(r0), "=r"(r1), "=r"(r2), "=r"(r3) : "r"(a));
}
__device__ __forceinline__ void mma16816(float* c, uint32_t a0, uint32_t a1, uint32_t a2, uint32_t a3,
                                         uint32_t b0, uint32_t b1) {
    asm volatile("mma.sync.aligned.m16n8k16.row.col.f32.f16.f16.f32 "
                 "{%0,%1,%2,%3}, {%4,%5,%6,%7}, {%8,%9}, {%0,%1,%2,%3};"
                 : "+f"(c[0]), "+f"(c[1]), "+f"(c[2]), "+f"(c[3])
                 : "r"(a0), "r"(a1), "r"(a2), "r"(a3), "r"(b0), "r"(b1));
}
__device__ __forceinline__ uint32_t h2u(__half2 h) { return *reinterpret_cast<uint32_t*>(&h); }

__device__ __forceinline__ void cp16(uint32_t dst, const void* src) {
    asm volatile("cp.async.cg.shared.global [%0], [%1], 16;" :: "r"(dst), "l"(src));
}
__device__ __forceinline__ void cp_commit() { asm volatile("cp.async.commit_group;"); }
template <int N>
__device__ __forceinline__ void cp_wait() { asm volatile("cp.async.wait_group %0;" :: "n"(N)); }

// ---------------------------------------------------------------------------
// k/v fp32 -> fp16
// ---------------------------------------------------------------------------
__global__ void convert_kv_kernel(const float* __restrict__ k, const float* __restrict__ v) {
    size_t i = (size_t)blockIdx.x * blockDim.x + threadIdx.x;
    size_t n4 = (size_t)CB * CLK * CD / 4;
    if (i >= n4) return;
    float4 a = reinterpret_cast<const float4*>(k)[i];
    float4 b = reinterpret_cast<const float4*>(v)[i];
    __half2* kh2 = reinterpret_cast<__half2*>(g_kh);
    __half2* vh2 = reinterpret_cast<__half2*>(g_vh);
    kh2[2 * i]     = __floats2half2_rn(a.x, a.y);
    kh2[2 * i + 1] = __floats2half2_rn(a.z, a.w);
    vh2[2 * i]     = __floats2half2_rn(b.x, b.y);
    vh2[2 * i + 1] = __floats2half2_rn(b.z, b.w);
}

// ---------------------------------------------------------------------------
// qw kernel: qw = (q @ w) * SCALE -> g_qwh fp16.  grid (CLQ/128, CB)
// ---------------------------------------------------------------------------
extern __shared__ char smem_raw[];

__global__ void __launch_bounds__(NTHREADS, 1)
qw_kernel(const float* __restrict__ q, const float* __restrict__ w) {
    __half* sQ = reinterpret_cast<__half*>(smem_raw);           // 128 x STRIDE
    __half* sW = sQ + 128 * STRIDE;                             // 64 x STRIDE

    const int tid  = threadIdx.x;
    const int lane = tid & 31;
    const int wid  = tid >> 5;
    const int b     = blockIdx.y;
    const int qbase = blockIdx.x * 128;
    const int wrow  = wid * 16;
    const int quad  = lane >> 2;
    const int qc    = lane & 3;

    const uint32_t smemB = (uint32_t)__cvta_generic_to_shared(smem_raw);
    const uint32_t aPat = (uint32_t)(((wrow + (lane & 15)) * STRIDE + ((lane >> 4) << 3)) * 2);
    const uint32_t bPatT = (uint32_t)(((((lane & 7) + (((lane >> 3) & 1) << 3)) * STRIDE) +
                                      ((lane >> 4) << 3)) * 2);

    {
        const float4* qg = reinterpret_cast<const float4*>(q + ((size_t)b * CLQ + qbase) * CD);
#pragma unroll
        for (int i = 0; i < 32; i++) {
            int e = tid + i * NTHREADS;
            int row = e >> 6, c4 = e & 63;
            float4 f = qg[row * 64 + c4];
            __half2* d = reinterpret_cast<__half2*>(sQ + row * STRIDE + c4 * 4);
            d[0] = __floats2half2_rn(f.x, f.y);
            d[1] = __floats2half2_rn(f.z, f.w);
        }
    }

    float oacc[32][4];
#pragma unroll
    for (int i = 0; i < 32; i++)
#pragma unroll
        for (int j = 0; j < 4; j++) oacc[i][j] = 0.f;

    const uint32_t bBaseW = smemB + (uint32_t)(128 * STRIDE * 2) + bPatT;
    for (int wb = 0; wb < 4; wb++) {
        __syncthreads();
        const float4* wg = reinterpret_cast<const float4*>(w + (size_t)wb * 64 * CD);
#pragma unroll
        for (int i = 0; i < 16; i++) {
            int e = tid + i * NTHREADS;
            int row = e >> 6, c4 = e & 63;
            float4 f = wg[row * 64 + c4];
            __half2* d = reinterpret_cast<__half2*>(sW + row * STRIDE + c4 * 4);
            d[0] = __floats2half2_rn(f.x, f.y);
            d[1] = __floats2half2_rn(f.z, f.w);
        }
        __syncthreads();
#pragma unroll
        for (int kk = 0; kk < 4; kk++) {
            uint32_t a0, a1, a2, a3;
            ldm4(a0, a1, a2, a3, smemB + aPat + (uint32_t)((wb * 64 + kk * 16) * 2));
#pragma unroll
            for (int nt2 = 0; nt2 < 16; nt2++) {
                uint32_t b0, b1, b2, b3;
                ldm4t(b0, b1, b2, b3, bBaseW + (uint32_t)((kk * 16 * STRIDE + nt2 * 16) * 2));
                mma16816(oacc[nt2 * 2],     a0, a1, a2, a3, b0, b1);
                mma16816(oacc[nt2 * 2 + 1], a0, a1, a2, a3, b2, b3);
            }
        }
    }

    __half2* qwRow0 = reinterpret_cast<__half2*>(g_qwh + ((size_t)b * CLQ + qbase + wrow + quad) * CD);
    __half2* qwRow1 = qwRow0 + 4 * CD;
#pragma unroll
    for (int nt = 0; nt < 32; nt++) {
        int c2 = (nt * 8 + qc * 2) >> 1;
        qwRow0[c2] = __floats2half2_rn(oacc[nt][0] * SCALE, oacc[nt][1] * SCALE);
        qwRow1[c2] = __floats2half2_rn(oacc[nt][2] * SCALE, oacc[nt][3] * SCALE);
    }
}

// ---------------------------------------------------------------------------
// fused kernel: per KV tile: S = qw@k^T -> u = exp(masked S) -> att (unnorm),
// u_h -> smem, l += rowsum(u), O += u_h @ V. Epilogue: out = O * invl.
// grid (CLQ/64, CB), 256 threads, 2 CTAs/SM.
// ---------------------------------------------------------------------------
__global__ void __launch_bounds__(NTHREADS, 2)
fused_kernel(const int* __restrict__ kidx, float* __restrict__ out, float* __restrict__ att) {
    const int tid  = threadIdx.x;
    const int lane = tid & 31;
    const int wid  = tid >> 5;
    const int rg   = wid & 3;     // S phase: 16-row group
    const int ch   = wid >> 2;    // S phase: 32-col half
    const int b     = blockIdx.y;
    const int qbase = blockIdx.x * QT;
    const int quad  = lane >> 2;
    const int qc    = lane & 3;

    const uint32_t smemB = (uint32_t)__cvta_generic_to_shared(smem_raw);
    float* redF  = reinterpret_cast<float*>(smem_raw + SM_RED);
    float* invlS = reinterpret_cast<float*>(smem_raw + SM_INV);

    // ldmatrix patterns
    const uint32_t aPat  = (uint32_t)(((rg * 16 + (lane & 15)) * STRIDE + ((lane >> 4) << 3)) * 2);
    const uint32_t bPatK = (uint32_t)(((((lane & 7) + ((lane >> 4) << 3)) * STRIDE) +
                                      (((lane >> 3) & 1) << 3)) * 2);
    const uint32_t bPatT = (uint32_t)(((((lane & 7) + (((lane >> 3) & 1) << 3)) * STRIDE) +
                                      ((lane >> 4) << 3)) * 2);
    const uint32_t uPatA = (uint32_t)(((lane & 15) * USTRIDE + ((lane >> 4) << 3)) * 2);
    const uint32_t slotB[2] = { smemB + SM_B0, smemB + SM_B1 };

    const __half* khg = g_kh + (size_t)b * CLK * CD;
    const __half* vhg = g_vh + (size_t)b * CLK * CD;
    const int*   maskg = kidx + (size_t)b * CLK;

    auto load_k = [&](int kt, int s) {
        const char* src = reinterpret_cast<const char*>(khg + (size_t)kt * KT * CD);
#pragma unroll
        for (int i = 0; i < 8; i++) {
            int e = tid + i * NTHREADS;
            int row = e >> 5, c = e & 31;
            cp16(slotB[s] + (uint32_t)(row * 528 + c * 16), src + row * 512 + c * 16);
        }
    };

    // ---- prologue: stage qw (group with K0), then K1 ----
    {
        const char* src = reinterpret_cast<const char*>(g_qwh + ((size_t)b * CLQ + qbase) * CD);
#pragma unroll
        for (int i = 0; i < 8; i++) {
            int e = tid + i * NTHREADS;
            int row = e >> 5, c = e & 31;
            cp16(smemB + SM_QW + (uint32_t)(row * 528 + c * 16), src + row * 512 + c * 16);
        }
    }
    load_k(0, 0);
    cp_commit();
    load_k(1, 1);
    cp_commit();
    cp_wait<1>();   // qw + K0 ready
    __syncthreads();

    float oacc[16][4];
#pragma unroll
    for (int i = 0; i < 16; i++)
#pragma unroll
        for (int j = 0; j < 4; j++) oacc[i][j] = 0.f;
    float lsum0 = 0.f, lsum1 = 0.f;

    float* attRow0 = att + ((size_t)b * CLQ + qbase + rg * 16 + quad) * CLK;
    float* attRow1 = attRow0 + (size_t)8 * CLK;
    __half2* uhRow0 = reinterpret_cast<__half2*>(
        smem_raw + SM_UH + ((rg * 16 + quad) * USTRIDE) * 2);
    __half2* uhRow1 = reinterpret_cast<__half2*>(
        smem_raw + SM_UH + ((rg * 16 + quad + 8) * USTRIDE) * 2);

#pragma unroll 1
    for (int kt = 0; kt < NT; kt++) {
        const uint32_t kslot = slotB[kt & 1];

        // mask for this tile (L2-resident after first CTA; plenty of latency slack)
        int2 mcur[4];
#pragma unroll
        for (int nt = 0; nt < 4; nt++)
            mcur[nt] = *reinterpret_cast<const int2*>(maskg + kt * KT + ch * 32 + nt * 8 + qc * 2);

        // ---- S mma: warp tile 16 q-rows x 32 kv-cols, k-dim 256 ----
        float sacc[4][4];
#pragma unroll
        for (int i = 0; i < 4; i++)
#pragma unroll
            for (int j = 0; j < 4; j++) sacc[i][j] = 0.f;
        const uint32_t bBase = kslot + bPatK + (uint32_t)(ch * 32 * STRIDE * 2);
#pragma unroll
        for (int kc = 0; kc < 16; kc++) {
            uint32_t a0, a1, a2, a3;
            ldm4(a0, a1, a2, a3, smemB + SM_QW + aPat + (uint32_t)(kc * 32));
#pragma unroll
            for (int nt2 = 0; nt2 < 2; nt2++) {
                uint32_t b0, b1, b2, b3;
                ldm4(b0, b1, b2, b3, bBase + (uint32_t)((nt2 * 16 * STRIDE + kc * 16) * 2));
                mma16816(sacc[nt2 * 2],     a0, a1, a2, a3, b0, b1);
                mma16816(sacc[nt2 * 2 + 1], a0, a1, a2, a3, b2, b3);
            }
        }
        __syncthreads();   // B1: all warps done reading K[kt] from kslot

        // ---- V[kt] into the retiring slot ----
        {
            const char* src = reinterpret_cast<const char*>(vhg + (size_t)kt * KT * CD);
#pragma unroll
            for (int i = 0; i < 8; i++) {
                int e = tid + i * NTHREADS;
                int row = e >> 5, c = e & 31;
                cp16(kslot + (uint32_t)(row * 528 + c * 16), src + row * 512 + c * 16);
            }
            cp_commit();
        }

        // ---- u = exp(masked s); att <- u; u_h -> smem; l += ----
#pragma unroll
        for (int nt = 0; nt < 4; nt++) {
            int c0 = kt * KT + ch * 32 + nt * 8 + qc * 2;
            float u0 = mcur[nt].x ? fast_ex2(sacc[nt][0] * LOG2E) : 0.f;
            float u1 = mcur[nt].y ? fast_ex2(sacc[nt][1] * LOG2E) : 0.f;
            float u2 = mcur[nt].x ? fast_ex2(sacc[nt][2] * LOG2E) : 0.f;
            float u3 = mcur[nt].y ? fast_ex2(sacc[nt][3] * LOG2E) : 0.f;
            *reinterpret_cast<float2*>(attRow0 + c0) = make_float2(u0, u1);
            *reinterpret_cast<float2*>(attRow1 + c0) = make_float2(u2, u3);
            lsum0 += u0 + u1;
            lsum1 += u2 + u3;
            int uc = (ch * 32 + nt * 8 + qc * 2) >> 1;
            uhRow0[uc] = __floats2half2_rn(u0, u1);
            uhRow1[uc] = __floats2half2_rn(u2, u3);
        }

        cp_wait<0>();      // V[kt] (and K[kt+1]) complete
        __syncthreads();   // B2: u_h + V visible to all warps

        // ---- PV mma: warp = 64 q-rows x 32 d-cols (d-base = wid*32) ----
        const uint32_t vB = kslot + bPatT + (uint32_t)(wid * 64);
#pragma unroll
        for (int kc2 = 0; kc2 < 4; kc2++) {
            uint32_t a[4][4];
#pragma unroll
            for (int mblk = 0; mblk < 4; mblk++)
                ldm4(a[mblk][0], a[mblk][1], a[mblk][2], a[mblk][3],
                     smemB + SM_UH + uPatA + (uint32_t)(mblk * 16 * USTRIDE * 2 + kc2 * 32));
#pragma unroll
            for (int nt2 = 0; nt2 < 2; nt2++) {
                uint32_t b0, b1, b2, b3;
                ldm4t(b0, b1, b2, b3, vB + (uint32_t)((kc2 * 16 * STRIDE + nt2 * 16) * 2));
#pragma unroll
                for (int mblk = 0; mblk < 4; mblk++) {
                    mma16816(oacc[mblk * 4 + nt2 * 2],     a[mblk][0], a[mblk][1], a[mblk][2], a[mblk][3], b0, b1);
                    mma16816(oacc[mblk * 4 + nt2 * 2 + 1], a[mblk][0], a[mblk][1], a[mblk][2], a[mblk][3], b2, b3);
                }
            }
        }
        __syncthreads();   // B3: V slot consumed

        if (kt + 2 < NT) { load_k(kt + 2, kt & 1); cp_commit(); }
    }

    // ---- l reduction -> invl ----
    lsum0 += __shfl_xor_sync(0xffffffffu, lsum0, 1);
    lsum0 += __shfl_xor_sync(0xffffffffu, lsum0, 2);
    lsum1 += __shfl_xor_sync(0xffffffffu, lsum1, 1);
    lsum1 += __shfl_xor_sync(0xffffffffu, lsum1, 2);
    if (qc == 0) {
        redF[ch * 64 + rg * 16 + quad]     = lsum0;
        redF[ch * 64 + rg * 16 + quad + 8] = lsum1;
    }
    __syncthreads();
    if (tid < 64) {
        float il = 1.0f / (redF[tid] + redF[64 + tid]);
        invlS[tid] = il;
        g_il[(size_t)b * CLQ + qbase + tid] = il;
    }
    __syncthreads();

    // ---- epilogue: out = O * invl ----
#pragma unroll
    for (int mblk = 0; mblk < 4; mblk++) {
        int row0 = mblk * 16 + quad;
        float il0 = invlS[row0], il1 = invlS[row0 + 8];
        float* o0 = out + ((size_t)b * CLQ + qbase + row0) * CD + wid * 32;
        float* o1 = o0 + 8 * CD;
#pragma unroll
        for (int ns = 0; ns < 4; ns++) {
            int col = ns * 8 + qc * 2;
            *reinterpret_cast<float2*>(o0 + col) =
                make_float2(oacc[mblk * 4 + ns][0] * il0, oacc[mblk * 4 + ns][1] * il0);
            *reinterpret_cast<float2*>(o1 + col) =
                make_float2(oacc[mblk * 4 + ns][2] * il1, oacc[mblk * 4 + ns][3] * il1);
        }
    }
}

// ---------------------------------------------------------------------------
// rescale kernel: att *= invl[row]  (pure stream)
// ---------------------------------------------------------------------------
__global__ void rescale_kernel(float* __restrict__ att) {
    unsigned idx = blockIdx.x * 256u + threadIdx.x;   // float4 index, < 16.8M
    unsigned row = idx >> 10;                         // CLK/4 = 1024 float4 per row
    float il = g_il[row];
    float4 v = reinterpret_cast<float4*>(att)[idx];
    v.x *= il; v.y *= il; v.z *= il; v.w *= il;
    reinterpret_cast<float4*>(att)[idx] = v;
}

// ---------------------------------------------------------------------------
// launch
// ---------------------------------------------------------------------------
extern "C" void kernel_launch(void* const* d_in, const int* in_sizes, int n_in,
                              void* d_out, int out_size) {
    const float* q    = (const float*)d_in[0];
    const float* k    = (const float*)d_in[1];
    const float* v    = (const float*)d_in[2];
    const int*   kidx = (const int*)d_in[3];
    const float* w    = (const float*)d_in[4];

    float* out = (float*)d_out;
    float* att = out + (size_t)CB * CLQ * CD;

    size_t n4 = (size_t)CB * CLK * CD / 4;
    convert_kv_kernel<<<(unsigned)((n4 + 255) / 256), 256>>>(k, v);

    cudaFuncSetAttribute(qw_kernel, cudaFuncAttributeMaxDynamicSharedMemorySize, 101376);
    qw_kernel<<<dim3(CLQ / 128, CB), NTHREADS, 101376>>>(q, w);

    cudaFuncSetAttribute(fused_kernel, cudaFuncAttributeMaxDynamicSharedMemorySize, SM_FUSED_TOTAL);
    fused_kernel<<<dim3(CLQ / QT, CB), NTHREADS, SM_FUSED_TOTAL>>>(kidx, out, att);

    unsigned n4att = (unsigned)((size_t)CB * CLQ * CLK / 4);
    rescale_kernel<<<n4att / 256, 256>>>(att);
}

// round 9
// speedup vs baseline: 1.0254x; 1.0167x over previous
#include <cuda_runtime.h>
#include <cuda_fp16.h>
#include <cstdint>

// Problem constants
constexpr int CB  = 4;
constexpr int CLQ = 4096;
constexpr int CLK = 4096;
constexpr int CD  = 256;

constexpr int QT = 128;        // q rows per CTA (fused kernel)
constexpr int KT = 64;         // kv rows per tile
constexpr int NT = CLK / KT;   // 64 tiles
constexpr int STRIDE = 264;    // smem row stride (halfs) for 256-wide fp16 tiles
constexpr int NTHREADS = 256;

constexpr float SCALE = 0.0625f;
constexpr float LOG2E = 1.4426950408889634f;

// static device scratch (~25.3 MB)
__device__ __half g_kh[(size_t)CB * CLK * CD];
__device__ __half g_vh[(size_t)CB * CLK * CD];
__device__ __half g_qwh[(size_t)CB * CLQ * CD];   // qw * SCALE, fp16
__device__ float  g_il[(size_t)CB * CLQ];         // 1 / rowsum

// ---- fused-kernel smem layout (bytes), total 220160, 1 CTA/SM ----
constexpr int SM_QW   = 0;        // 128 x 528 = 67584  (qw tile, resident)
constexpr int SM_K0   = 67584;    // 64 x 528 = 33792
constexpr int SM_K1   = 101376;
constexpr int SM_V0   = 135168;
constexpr int SM_V1   = 168960;
constexpr int SM_MASK = 202752;   // 4096 ints = 16384
constexpr int SM_RED  = 219136;   // 128 floats = 512
constexpr int SM_INV  = 219648;   // 128 floats = 512
constexpr int SM_FUSED_TOTAL = 220160;

// ---------------------------------------------------------------------------
// helpers
// ---------------------------------------------------------------------------
__device__ __forceinline__ float fast_ex2(float x) {
    float r; asm("ex2.approx.ftz.f32 %0, %1;" : "=f"(r) : "f"(x)); return r;
}
__device__ __forceinline__ void ldm4(uint32_t& r0, uint32_t& r1, uint32_t& r2, uint32_t& r3, uint32_t a) {
    asm volatile("ldmatrix.sync.aligned.m8n8.x4.shared.b16 {%0,%1,%2,%3}, [%4];"
                 : "=r"(r0), "=r"(r1), "=r"(r2), "=r"(r3) : "r"(a));
}
__device__ __forceinline__ void ldm4t(uint32_t& r0, uint32_t& r1, uint32_t& r2, uint32_t& r3, uint32_t a) {
    asm volatile("ldmatrix.sync.aligned.m8n8.x4.trans.shared.b16 {%0,%1,%2,%3}, [%4];"
                 : "=r"(r0), "=r"(r1), "=r"(r2), "=r"(r3) : "r"(a));
}
__device__ __forceinline__ void mma16816(float* c, uint32_t a0, uint32_t a1, uint32_t a2, uint32_t a3,
                                         uint32_t b0, uint32_t b1) {
    asm volatile("mma.sync.aligned.m16n8k16.row.col.f32.f16.f16.f32 "
                 "{%0,%1,%2,%3}, {%4,%5,%6,%7}, {%8,%9}, {%0,%1,%2,%3};"
                 : "+f"(c[0]), "+f"(c[1]), "+f"(c[2]), "+f"(c[3])
                 : "r"(a0), "r"(a1), "r"(a2), "r"(a3), "r"(b0), "r"(b1));
}
__device__ __forceinline__ uint32_t h2u(__half2 h) { return *reinterpret_cast<uint32_t*>(&h); }

__device__ __forceinline__ void cp16(uint32_t dst, const void* src) {
    asm volatile("cp.async.cg.shared.global [%0], [%1], 16;" :: "r"(dst), "l"(src));
}
__device__ __forceinline__ void cp_commit() { asm volatile("cp.async.commit_group;"); }
template <int N>
__device__ __forceinline__ void cp_wait() { asm volatile("cp.async.wait_group %0;" :: "n"(N)); }

// ---------------------------------------------------------------------------
// k/v fp32 -> fp16
// ---------------------------------------------------------------------------
__global__ void convert_kv_kernel(const float* __restrict__ k, const float* __restrict__ v) {
    size_t i = (size_t)blockIdx.x * blockDim.x + threadIdx.x;
    size_t n4 = (size_t)CB * CLK * CD / 4;
    if (i >= n4) return;
    float4 a = reinterpret_cast<const float4*>(k)[i];
    float4 b = reinterpret_cast<const float4*>(v)[i];
    __half2* kh2 = reinterpret_cast<__half2*>(g_kh);
    __half2* vh2 = reinterpret_cast<__half2*>(g_vh);
    kh2[2 * i]     = __floats2half2_rn(a.x, a.y);
    kh2[2 * i + 1] = __floats2half2_rn(a.z, a.w);
    vh2[2 * i]     = __floats2half2_rn(b.x, b.y);
    vh2[2 * i + 1] = __floats2half2_rn(b.z, b.w);
}

// ---------------------------------------------------------------------------
// qw kernel: qw = (q @ w) * SCALE -> g_qwh fp16.  grid (CLQ/128, CB)
// ---------------------------------------------------------------------------
extern __shared__ char smem_raw[];

__global__ void __launch_bounds__(NTHREADS, 1)
qw_kernel(const float* __restrict__ q, const float* __restrict__ w) {
    __half* sQ = reinterpret_cast<__half*>(smem_raw);           // 128 x STRIDE
    __half* sW = sQ + 128 * STRIDE;                             // 64 x STRIDE

    const int tid  = threadIdx.x;
    const int lane = tid & 31;
    const int wid  = tid >> 5;
    const int b     = blockIdx.y;
    const int qbase = blockIdx.x * 128;
    const int wrow  = wid * 16;
    const int quad  = lane >> 2;
    const int qc    = lane & 3;

    const uint32_t smemB = (uint32_t)__cvta_generic_to_shared(smem_raw);
    const uint32_t aPat = (uint32_t)(((wrow + (lane & 15)) * STRIDE + ((lane >> 4) << 3)) * 2);
    const uint32_t bPatT = (uint32_t)(((((lane & 7) + (((lane >> 3) & 1) << 3)) * STRIDE) +
                                      ((lane >> 4) << 3)) * 2);

    {
        const float4* qg = reinterpret_cast<const float4*>(q + ((size_t)b * CLQ + qbase) * CD);
#pragma unroll
        for (int i = 0; i < 32; i++) {
            int e = tid + i * NTHREADS;
            int row = e >> 6, c4 = e & 63;
            float4 f = qg[row * 64 + c4];
            __half2* d = reinterpret_cast<__half2*>(sQ + row * STRIDE + c4 * 4);
            d[0] = __floats2half2_rn(f.x, f.y);
            d[1] = __floats2half2_rn(f.z, f.w);
        }
    }

    float oacc[32][4];
#pragma unroll
    for (int i = 0; i < 32; i++)
#pragma unroll
        for (int j = 0; j < 4; j++) oacc[i][j] = 0.f;

    const uint32_t bBaseW = smemB + (uint32_t)(128 * STRIDE * 2) + bPatT;
    for (int wb = 0; wb < 4; wb++) {
        __syncthreads();
        const float4* wg = reinterpret_cast<const float4*>(w + (size_t)wb * 64 * CD);
#pragma unroll
        for (int i = 0; i < 16; i++) {
            int e = tid + i * NTHREADS;
            int row = e >> 6, c4 = e & 63;
            float4 f = wg[row * 64 + c4];
            __half2* d = reinterpret_cast<__half2*>(sW + row * STRIDE + c4 * 4);
            d[0] = __floats2half2_rn(f.x, f.y);
            d[1] = __floats2half2_rn(f.z, f.w);
        }
        __syncthreads();
#pragma unroll
        for (int kk = 0; kk < 4; kk++) {
            uint32_t a0, a1, a2, a3;
            ldm4(a0, a1, a2, a3, smemB + aPat + (uint32_t)((wb * 64 + kk * 16) * 2));
#pragma unroll
            for (int nt2 = 0; nt2 < 16; nt2++) {
                uint32_t b0, b1, b2, b3;
                ldm4t(b0, b1, b2, b3, bBaseW + (uint32_t)((kk * 16 * STRIDE + nt2 * 16) * 2));
                mma16816(oacc[nt2 * 2],     a0, a1, a2, a3, b0, b1);
                mma16816(oacc[nt2 * 2 + 1], a0, a1, a2, a3, b2, b3);
            }
        }
    }

    __half2* qwRow0 = reinterpret_cast<__half2*>(g_qwh + ((size_t)b * CLQ + qbase + wrow + quad) * CD);
    __half2* qwRow1 = qwRow0 + 4 * CD;
#pragma unroll
    for (int nt = 0; nt < 32; nt++) {
        int c2 = (nt * 8 + qc * 2) >> 1;
        qwRow0[c2] = __floats2half2_rn(oacc[nt][0] * SCALE, oacc[nt][1] * SCALE);
        qwRow1[c2] = __floats2half2_rn(oacc[nt][2] * SCALE, oacc[nt][3] * SCALE);
    }
}

// ---------------------------------------------------------------------------
// fused single-pass kernel: per KV tile:
//   S = qw@k^T -> u = exp(masked S) (registers) -> att (unnorm u),
//   l += rowsum(u), O += u@V (u fed to PV mma directly from registers).
// Epilogue: out = O * invl. grid (CLQ/128, CB), 256 threads, 1 CTA/SM.
// ---------------------------------------------------------------------------
__global__ void __launch_bounds__(NTHREADS, 1)
fused_kernel(const int* __restrict__ kidx, float* __restrict__ out, float* __restrict__ att) {
    const int tid  = threadIdx.x;
    const int lane = tid & 31;
    const int wid  = tid >> 5;
    const int b     = blockIdx.y;
    const int qbase = blockIdx.x * QT;
    const int wrow  = wid * 16;
    const int quad  = lane >> 2;
    const int qc    = lane & 3;

    const uint32_t smemB = (uint32_t)__cvta_generic_to_shared(smem_raw);
    int*   maskS = reinterpret_cast<int*>(smem_raw + SM_MASK);
    float* redF  = reinterpret_cast<float*>(smem_raw + SM_RED);
    float* invlS = reinterpret_cast<float*>(smem_raw + SM_INV);

    const uint32_t aPat  = (uint32_t)(((wrow + (lane & 15)) * STRIDE + ((lane >> 4) << 3)) * 2);
    const uint32_t bPatK = (uint32_t)(((((lane & 7) + ((lane >> 4) << 3)) * STRIDE) +
                                      (((lane >> 3) & 1) << 3)) * 2);
    const uint32_t bPatT = (uint32_t)(((((lane & 7) + (((lane >> 3) & 1) << 3)) * STRIDE) +
                                      ((lane >> 4) << 3)) * 2);
    const uint32_t kSlot[2] = { smemB + SM_K0, smemB + SM_K1 };
    const uint32_t vSlot[2] = { smemB + SM_V0, smemB + SM_V1 };

    const __half* khg = g_kh + (size_t)b * CLK * CD;
    const __half* vhg = g_vh + (size_t)b * CLK * CD;

    // one commit group per tile: {K[kt], V[kt]} (empty group when out of range)
    auto load_kv = [&](int kt) {
        if (kt < NT) {
            const char* ksrc = reinterpret_cast<const char*>(khg + (size_t)kt * KT * CD);
            const char* vsrc = reinterpret_cast<const char*>(vhg + (size_t)kt * KT * CD);
            uint32_t kd = kSlot[kt & 1], vd = vSlot[kt & 1];
#pragma unroll
            for (int i = 0; i < 8; i++) {
                int e = tid + i * NTHREADS;
                int row = e >> 5, c = e & 31;
                cp16(kd + (uint32_t)(row * 528 + c * 16), ksrc + row * 512 + c * 16);
                cp16(vd + (uint32_t)(row * 528 + c * 16), vsrc + row * 512 + c * 16);
            }
        }
        cp_commit();
    };

    // ---- prologue: qw (own group), then tiles 0 and 1; mask via plain st ----
    {
        const char* src = reinterpret_cast<const char*>(g_qwh + ((size_t)b * CLQ + qbase) * CD);
#pragma unroll
        for (int i = 0; i < 16; i++) {
            int e = tid + i * NTHREADS;      // 4096 chunks of 16B
            int row = e >> 5, c = e & 31;
            cp16(smemB + SM_QW + (uint32_t)(row * 528 + c * 16), src + row * 512 + c * 16);
        }
        cp_commit();
    }
    load_kv(0);
    load_kv(1);
#pragma unroll
    for (int i = 0; i < 4; i++) {
        int e = tid + i * NTHREADS;
        reinterpret_cast<int4*>(maskS)[e] =
            reinterpret_cast<const int4*>(kidx + (size_t)b * CLK)[e];
    }
    cp_wait<1>();       // qw + tile0 arrived; tile1 in flight
    __syncthreads();

    float oacc[32][4];
#pragma unroll
    for (int i = 0; i < 32; i++)
#pragma unroll
        for (int j = 0; j < 4; j++) oacc[i][j] = 0.f;
    float lsum0 = 0.f, lsum1 = 0.f;

    float* attRow0 = att + ((size_t)b * CLQ + qbase + wrow + quad) * CLK;
    float* attRow1 = attRow0 + (size_t)8 * CLK;

#pragma unroll 1
    for (int kt = 0; kt < NT; kt++) {
        const uint32_t kB = kSlot[kt & 1] + bPatK;
        const uint32_t vB = vSlot[kt & 1] + bPatT;

        // ---- S mma: warp = 16 q-rows x 64 kv-cols, k-dim 256 ----
        float sacc[8][4];
#pragma unroll
        for (int i = 0; i < 8; i++)
#pragma unroll
            for (int j = 0; j < 4; j++) sacc[i][j] = 0.f;
#pragma unroll
        for (int kc = 0; kc < 16; kc++) {
            uint32_t a0, a1, a2, a3;
            ldm4(a0, a1, a2, a3, smemB + SM_QW + aPat + (uint32_t)(kc * 32));
#pragma unroll
            for (int nt2 = 0; nt2 < 4; nt2++) {
                uint32_t b0, b1, b2, b3;
                ldm4(b0, b1, b2, b3, kB + (uint32_t)((nt2 * 16 * STRIDE + kc * 16) * 2));
                mma16816(sacc[nt2 * 2],     a0, a1, a2, a3, b0, b1);
                mma16816(sacc[nt2 * 2 + 1], a0, a1, a2, a3, b2, b3);
            }
        }

        // ---- u = exp(masked s); att <- u; l += ; keep u in sacc ----
#pragma unroll
        for (int nt = 0; nt < 8; nt++) {
            int c0 = nt * 8 + qc * 2;
            int m0 = maskS[kt * KT + c0], m1 = maskS[kt * KT + c0 + 1];
            float u0 = m0 ? fast_ex2(sacc[nt][0] * LOG2E) : 0.f;
            float u1 = m1 ? fast_ex2(sacc[nt][1] * LOG2E) : 0.f;
            float u2 = m0 ? fast_ex2(sacc[nt][2] * LOG2E) : 0.f;
            float u3 = m1 ? fast_ex2(sacc[nt][3] * LOG2E) : 0.f;
            *reinterpret_cast<float2*>(attRow0 + kt * KT + c0) = make_float2(u0, u1);
            *reinterpret_cast<float2*>(attRow1 + kt * KT + c0) = make_float2(u2, u3);
            lsum0 += u0 + u1;
            lsum1 += u2 + u3;
            sacc[nt][0] = u0; sacc[nt][1] = u1; sacc[nt][2] = u2; sacc[nt][3] = u3;
        }

        // ---- PV mma: A = u (registers, C-frag == A-frag layout), B = V ----
#pragma unroll
        for (int kc2 = 0; kc2 < 4; kc2++) {
            uint32_t a0 = h2u(__floats2half2_rn(sacc[2 * kc2][0],     sacc[2 * kc2][1]));
            uint32_t a1 = h2u(__floats2half2_rn(sacc[2 * kc2][2],     sacc[2 * kc2][3]));
            uint32_t a2 = h2u(__floats2half2_rn(sacc[2 * kc2 + 1][0], sacc[2 * kc2 + 1][1]));
            uint32_t a3 = h2u(__floats2half2_rn(sacc[2 * kc2 + 1][2], sacc[2 * kc2 + 1][3]));
#pragma unroll
            for (int nt2 = 0; nt2 < 16; nt2++) {
                uint32_t b0, b1, b2, b3;
                ldm4t(b0, b1, b2, b3, vB + (uint32_t)((kc2 * 16 * STRIDE + nt2 * 16) * 2));
                mma16816(oacc[nt2 * 2],     a0, a1, a2, a3, b0, b1);
                mma16816(oacc[nt2 * 2 + 1], a0, a1, a2, a3, b2, b3);
            }
        }

        __syncthreads();        // all warps done with slots kt
        load_kv(kt + 2);        // overwrite slots (kt&1); empty commit past end
        cp_wait<1>();           // tile kt+1 fully arrived
        __syncthreads();        // its data visible to all threads
    }

    // ---- l reduction -> invl ----
    lsum0 += __shfl_xor_sync(0xffffffffu, lsum0, 1);
    lsum0 += __shfl_xor_sync(0xffffffffu, lsum0, 2);
    lsum1 += __shfl_xor_sync(0xffffffffu, lsum1, 1);
    lsum1 += __shfl_xor_sync(0xffffffffu, lsum1, 2);
    if (qc == 0) {
        redF[wrow + quad]     = lsum0;
        redF[wrow + quad + 8] = lsum1;
    }
    __syncthreads();
    if (tid < 128) {
        float il = 1.0f / redF[tid];
        invlS[tid] = il;
        g_il[(size_t)b * CLQ + qbase + tid] = il;
    }
    __syncthreads();

    // ---- epilogue: out = O * invl ----
    const float il0 = invlS[wrow + quad];
    const float il1 = invlS[wrow + quad + 8];
    float* outRow0 = out + ((size_t)b * CLQ + qbase + wrow + quad) * CD;
    float* outRow1 = outRow0 + 8 * CD;
#pragma unroll
    for (int nt = 0; nt < 32; nt++) {
        int col = nt * 8 + qc * 2;
        *reinterpret_cast<float2*>(outRow0 + col) =
            make_float2(oacc[nt][0] * il0, oacc[nt][1] * il0);
        *reinterpret_cast<float2*>(outRow1 + col) =
            make_float2(oacc[nt][2] * il1, oacc[nt][3] * il1);
    }
}

// ---------------------------------------------------------------------------
// rescale kernel: att *= invl[row]  (pure stream)
// ---------------------------------------------------------------------------
__global__ void rescale_kernel(float* __restrict__ att) {
    unsigned idx = blockIdx.x * 256u + threadIdx.x;   // float4 index
    unsigned row = idx >> 10;                         // 1024 float4 per row
    float il = g_il[row];
    float4 v = reinterpret_cast<float4*>(att)[idx];
    v.x *= il; v.y *= il; v.z *= il; v.w *= il;
    reinterpret_cast<float4*>(att)[idx] = v;
}

// ---------------------------------------------------------------------------
// launch
// ---------------------------------------------------------------------------
extern "C" void kernel_launch(void* const* d_in, const int* in_sizes, int n_in,
                              void* d_out, int out_size) {
    const float* q    = (const float*)d_in[0];
    const float* k    = (const float*)d_in[1];
    const float* v    = (const float*)d_in[2];
    const int*   kidx = (const int*)d_in[3];
    const float* w    = (const float*)d_in[4];

    float* out = (float*)d_out;
    float* att = out + (size_t)CB * CLQ * CD;

    size_t n4 = (size_t)CB * CLK * CD / 4;
    convert_kv_kernel<<<(unsigned)((n4 + 255) / 256), 256>>>(k, v);

    cudaFuncSetAttribute(qw_kernel, cudaFuncAttributeMaxDynamicSharedMemorySize, 101376);
    qw_kernel<<<dim3(CLQ / 128, CB), NTHREADS, 101376>>>(q, w);

    cudaFuncSetAttribute(fused_kernel, cudaFuncAttributeMaxDynamicSharedMemorySize, SM_FUSED_TOTAL);
    fused_kernel<<<dim3(CLQ / QT, CB), NTHREADS, SM_FUSED_TOTAL>>>(kidx, out, att);

    unsigned n4att = (unsigned)((size_t)CB * CLQ * CLK / 4);
    rescale_kernel<<<n4att / 256, 256>>>(att);
}